// round 3
// baseline (speedup 1.0000x reference)
#include <cuda_runtime.h>
#include <math.h>

// Problem constants (fixed by the dataset)
#define A_   16
#define SK_  2048
#define SQ_  2048
#define D_   128
#define IDM_ 128
#define RR_  3
#define EPARTS 4
// T_ANNEAL = 10, t_ANNEAL = 0

// ---------------------------------------------------------------------------
// Scratch (device globals — no allocation allowed)
// ---------------------------------------------------------------------------
// Partial folded projections: g_Mp[side][ep][a][d*3+r]; code sums the 4 eparts.
__device__ float  g_Mp[2][EPARTS][A_ * IDM_ * RR_];
__device__ float  g_c[2][A_ * RR_];          // folded bias projections
// Hash codes, padded to float4 per row.  K-codes pre-scaled by 1/R.
__device__ float4 g_code[2][A_ * SK_];       // [0] = Kc/3, [1] = Qc

// ---------------------------------------------------------------------------
// Kernel 1: fold Wk/Wq + bias through W[a].
// Grid: 128 blocks = (side, a, epart).  Block: 128 threads (one per d).
// Each thread reduces its 32-e slice; partials summed by code_kernel.
// ---------------------------------------------------------------------------
__global__ void __launch_bounds__(128) prep_kernel(
        const float* __restrict__ Wk, const float* __restrict__ bk,
        const float* __restrict__ Wq, const float* __restrict__ bq,
        const float* __restrict__ W) {
    const int ep   = blockIdx.x & (EPARTS - 1);
    const int a    = (blockIdx.x >> 2) & 15;
    const int side = blockIdx.x >> 6;        // 0 = K, 1 = Q
    const float* Wx = side ? Wq : Wk;
    const float* bx = side ? bq : bk;

    const int d = threadIdx.x;               // 0..127

    __shared__ float Wsh[32 * RR_];          // W[a] slice for this epart: [32,3]
    if (d < 32 * RR_) Wsh[d] = W[a * IDM_ * RR_ + ep * 32 * RR_ + d];
    __syncthreads();

    float a0 = 0.f, a1 = 0.f, a2 = 0.f;
#pragma unroll 8
    for (int i = 0; i < 32; i++) {
        int e = ep * 32 + i;
        float w = Wx[e * D_ + d];            // coalesced across threads
        a0 = fmaf(w, Wsh[i * 3 + 0], a0);
        a1 = fmaf(w, Wsh[i * 3 + 1], a1);
        a2 = fmaf(w, Wsh[i * 3 + 2], a2);
    }
    int base = a * (IDM_ * RR_) + d * RR_;
    g_Mp[side][ep][base + 0] = a0;
    g_Mp[side][ep][base + 1] = a1;
    g_Mp[side][ep][base + 2] = a2;

    // bias fold: ep==0 block's warp 0 computes c[r] over all 128 e's
    if (ep == 0 && d < 32) {
        float c0 = 0.f, c1 = 0.f, c2 = 0.f;
#pragma unroll
        for (int e = d; e < IDM_; e += 32) {
            float b = bx[e];
            c0 = fmaf(b, W[a * IDM_ * RR_ + e * 3 + 0], c0);
            c1 = fmaf(b, W[a * IDM_ * RR_ + e * 3 + 1], c1);
            c2 = fmaf(b, W[a * IDM_ * RR_ + e * 3 + 2], c2);
        }
#pragma unroll
        for (int o = 16; o > 0; o >>= 1) {
            c0 += __shfl_xor_sync(0xffffffffu, c0, o);
            c1 += __shfl_xor_sync(0xffffffffu, c1, o);
            c2 += __shfl_xor_sync(0xffffffffu, c2, o);
        }
        if (d == 0) {
            g_c[side][a * RR_ + 0] = c0;
            g_c[side][a * RR_ + 1] = c1;
            g_c[side][a * RR_ + 2] = c2;
        }
    }
}

// ---------------------------------------------------------------------------
// Kernel 2: compute hash codes.  One warp per sequence row (K and Q).
// Sums the 4 prep partials at load time (L2-resident).
// Kc pre-scaled by 1/R so the main kernel's dot needs no extra multiply.
// ---------------------------------------------------------------------------
__global__ void code_kernel(const float* __restrict__ K, const float* __restrict__ Q) {
    int warp = (blockIdx.x * blockDim.x + threadIdx.x) >> 5;
    int lane = threadIdx.x & 31;
    int which = (warp >= A_ * SK_) ? 1 : 0;
    int row   = which ? (warp - A_ * SK_) : warp;     // a*2048 + s
    int a     = row >> 11;

    const float* X = which ? Q : K;
    const float4 x = reinterpret_cast<const float4*>(X)[row * (D_ / 4) + lane];

    // sum partial M's: 12 floats per lane per epart
    float4 m0 = make_float4(0.f, 0.f, 0.f, 0.f);
    float4 m1 = m0, m2 = m0;
#pragma unroll
    for (int p = 0; p < EPARTS; p++) {
        const float* M = &g_Mp[which][p][a * (IDM_ * RR_) + lane * 12];
        float4 t0 = *reinterpret_cast<const float4*>(M);
        float4 t1 = *reinterpret_cast<const float4*>(M + 4);
        float4 t2 = *reinterpret_cast<const float4*>(M + 8);
        m0.x += t0.x; m0.y += t0.y; m0.z += t0.z; m0.w += t0.w;
        m1.x += t1.x; m1.y += t1.y; m1.z += t1.z; m1.w += t1.w;
        m2.x += t2.x; m2.y += t2.y; m2.z += t2.z; m2.w += t2.w;
    }

    // partial dots for r = 0,1,2  (M layout d-major: [d0r0 d0r1 d0r2 d1r0 ...])
    float p0 = x.x * m0.x + x.y * m0.w + x.z * m1.z + x.w * m2.y;
    float p1 = x.x * m0.y + x.y * m1.x + x.z * m1.w + x.w * m2.z;
    float p2 = x.x * m0.z + x.y * m1.y + x.z * m2.x + x.w * m2.w;

#pragma unroll
    for (int o = 16; o > 0; o >>= 1) {
        p0 += __shfl_xor_sync(0xffffffffu, p0, o);
        p1 += __shfl_xor_sync(0xffffffffu, p1, o);
        p2 += __shfl_xor_sync(0xffffffffu, p2, o);
    }
    if (lane == 0) {
        const float* c = &g_c[which][a * RR_];
        float scale = which ? 1.0f : (1.0f / 3.0f);   // fold /R into Kc
        float v0 = tanhf((p0 + c[0]) * 0.1f) * scale;
        float v1 = tanhf((p1 + c[1]) * 0.1f) * scale;
        float v2 = tanhf((p2 + c[2]) * 0.1f) * scale;
        g_code[which][row] = make_float4(v0, v1, v2, 0.f);
    }
}

// ---------------------------------------------------------------------------
// Kernel 3: main pass.  out[a,t,s] = x * sigmoid(x/10),  x = Qc(t)·Kc(s)/R.
// |x| < 1  =>  sigmoid(x/10) ~= 0.5 + (x/10)/4 - (x/10)^3/48   (abs err ~2e-8)
// Tile: 8 t-rows x 1024 s-cols per 256-thread block; float4 streaming stores.
// ---------------------------------------------------------------------------
__device__ __forceinline__ float pc_fn(const float4 q, const float4 k) {
    float x  = fmaf(q.x, k.x, fmaf(q.y, k.y, q.z * k.z));      // Kc already /3
    float t  = x * x;
    float sg = fmaf(x, fmaf(t, -2.0833333e-5f, 0.025f), 0.5f); // sigmoid(x/10)
    return x * sg;
}

__global__ void __launch_bounds__(256) pc_kernel(float* __restrict__ out) {
    const int a     = blockIdx.z;
    const int tbase = blockIdx.y * 8;
    const int sbase = blockIdx.x * 1024;
    const int tid   = threadIdx.x;

    __shared__ float4 kc_sh[1024];
    __shared__ float4 qc_sh[8];

#pragma unroll
    for (int i = 0; i < 4; i++)
        kc_sh[tid + 256 * i] = g_code[0][a * SK_ + sbase + tid + 256 * i];
    if (tid < 8)
        qc_sh[tid] = g_code[1][a * SQ_ + tbase + tid];
    __syncthreads();

    const float4 k0 = kc_sh[tid * 4 + 0];
    const float4 k1 = kc_sh[tid * 4 + 1];
    const float4 k2 = kc_sh[tid * 4 + 2];
    const float4 k3 = kc_sh[tid * 4 + 3];

    size_t obase = ((size_t)(a * SQ_ + tbase)) * SK_ + (size_t)(sbase + tid * 4);
#pragma unroll
    for (int j = 0; j < 8; j++) {
        const float4 q = qc_sh[j];        // broadcast LDS
        float4 o;
        o.x = pc_fn(q, k0);
        o.y = pc_fn(q, k1);
        o.z = pc_fn(q, k2);
        o.w = pc_fn(q, k3);
        __stcs(reinterpret_cast<float4*>(out + obase + (size_t)j * SK_), o);
    }
}

// ---------------------------------------------------------------------------
// Launch
// ---------------------------------------------------------------------------
extern "C" void kernel_launch(void* const* d_in, const int* in_sizes, int n_in,
                              void* d_out, int out_size) {
    const float* K  = (const float*)d_in[0];
    const float* Q  = (const float*)d_in[1];
    const float* Wk = (const float*)d_in[2];
    const float* bk = (const float*)d_in[3];
    const float* Wq = (const float*)d_in[4];
    const float* bq = (const float*)d_in[5];
    const float* W  = (const float*)d_in[6];
    float* out = (float*)d_out;

    prep_kernel<<<2 * A_ * EPARTS, 128>>>(Wk, bk, Wq, bq, W);
    // 2 * 16 * 2048 rows, 1 warp per row, 8 warps per block
    code_kernel<<<(2 * A_ * SK_) / 8, 256>>>(K, Q);
    pc_kernel<<<dim3(SK_ / 1024, SQ_ / 8, A_), 256>>>(out);
}